// round 1
// baseline (speedup 1.0000x reference)
#include <cuda_runtime.h>
#include <cstdint>

#define B  64
#define N  65536
#define C  6
#define NT 1024
#define PPT (N / NT)   // 64 points per thread

// Scratch (allocation-free rule: __device__ globals)
__device__ int g_idx[B * N];   // compacted kept indices per batch
__device__ int g_nv[B];        // num_valid per batch

// One block per batch: FPS (4 centers, recompute min-dist each step) +
// keep flags + stable block scan + compaction.
__global__ __launch_bounds__(NT) void fps_compact_kernel(const float* __restrict__ pts) {
    const int b = blockIdx.x;
    const float* P = pts + (size_t)b * N * C;
    const int t = threadIdx.x;

    __shared__ float cx[4], cy[4], cz[4];
    __shared__ float rv[32];
    __shared__ int   ri[32];
    __shared__ int   swarp[32];

    // center 0 = point 0 (pointnet2 convention)
    if (t == 0) { cx[0] = P[0]; cy[0] = P[1]; cz[0] = P[2]; }
    __syncthreads();

    // ---- FPS: 3 argmax steps produce centers 1..3 ----
    for (int s = 0; s < 3; s++) {
        float best = -1.0f;
        int   bi   = 0;
        #pragma unroll 4
        for (int k = 0; k < PPT; k++) {
            const int i = t + k * NT;                 // strided = coalesced
            const float* p = P + (size_t)i * C;
            const float2 xy = *(const float2*)p;      // 8B-aligned (24B rows)
            const float  z  = p[2];
            float md = 1e10f;
            for (int cc = 0; cc <= s; cc++) {
                const float dx = xy.x - cx[cc];
                const float dy = xy.y - cy[cc];
                const float dz = z    - cz[cc];
                md = fminf(md, dx * dx + dy * dy + dz * dz);
            }
            if (md > best) { best = md; bi = i; }     // strict > : first-index tie-break (i ascends in k)
        }
        // warp argmax (value desc, index asc on ties)
        #pragma unroll
        for (int o = 16; o; o >>= 1) {
            const float v = __shfl_down_sync(0xffffffffu, best, o);
            const int   j = __shfl_down_sync(0xffffffffu, bi,   o);
            if (v > best || (v == best && j < bi)) { best = v; bi = j; }
        }
        if ((t & 31) == 0) { rv[t >> 5] = best; ri[t >> 5] = bi; }
        __syncthreads();
        if (t < 32) {
            best = rv[t]; bi = ri[t];
            #pragma unroll
            for (int o = 16; o; o >>= 1) {
                const float v = __shfl_down_sync(0xffffffffu, best, o);
                const int   j = __shfl_down_sync(0xffffffffu, bi,   o);
                if (v > best || (v == best && j < bi)) { best = v; bi = j; }
            }
            if (t == 0) {
                const float* p = P + (size_t)bi * C;
                cx[s + 1] = p[0]; cy[s + 1] = p[1]; cz[s + 1] = p[2];
            }
        }
        __syncthreads();
    }

    // ---- keep flags over contiguous per-thread chunk (stable order) ----
    const int base = t * PPT;
    unsigned long long mask = 0ull;
    int cnt = 0;
    #pragma unroll 4
    for (int k = 0; k < PPT; k++) {
        const int i = base + k;
        const float* p = P + (size_t)i * C;
        const float2 xy = *(const float2*)p;
        const float  z  = p[2];
        float md = 1e10f;
        #pragma unroll
        for (int cc = 0; cc < 4; cc++) {
            const float dx = xy.x - cx[cc];
            const float dy = xy.y - cy[cc];
            const float dz = z    - cz[cc];
            md = fminf(md, dx * dx + dy * dy + dz * dz);
        }
        if (__fsqrt_rn(md) >= 0.2f) {   // correctly-rounded sqrt == jnp.linalg.norm compare
            mask |= 1ull << k;
            cnt++;
        }
    }

    // ---- block exclusive scan over 1024 thread counts ----
    const int lane = t & 31, w = t >> 5;
    int inc = cnt;
    #pragma unroll
    for (int o = 1; o < 32; o <<= 1) {
        const int u = __shfl_up_sync(0xffffffffu, inc, o);
        if (lane >= o) inc += u;
    }
    if (lane == 31) swarp[w] = inc;
    __syncthreads();
    if (t < 32) {
        int v2 = swarp[t];
        #pragma unroll
        for (int o = 1; o < 32; o <<= 1) {
            const int u = __shfl_up_sync(0xffffffffu, v2, o);
            if (t >= o) v2 += u;
        }
        swarp[t] = v2;
    }
    __syncthreads();

    int off = inc - cnt + (w ? swarp[w - 1] : 0);
    int* ob = g_idx + b * N;
    for (int k = 0; k < PPT; k++) {
        if ((mask >> k) & 1ull) ob[off++] = base + k;
    }
    if (t == 0) g_nv[b] = swarp[31];
}

// out[b, j, :] = points[b, kept[j % nv], :]  (zeros if nv == 0)
__global__ __launch_bounds__(256) void gather_kernel(const float* __restrict__ pts,
                                                     float* __restrict__ out) {
    const int tid = blockIdx.x * blockDim.x + threadIdx.x;   // one thread per point row
    if (tid >= B * N) return;
    const int b = tid >> 16;
    const int j = tid & (N - 1);
    const int nv = g_nv[b];
    float2* d = (float2*)(out + (size_t)tid * C);
    if (nv == 0) {
        const float2 z = make_float2(0.f, 0.f);
        d[0] = z; d[1] = z; d[2] = z;
        return;
    }
    const int k   = j % nv;
    const int src = g_idx[(b << 16) + k];
    const float2* sp = (const float2*)(pts + ((size_t)(b << 16) + src) * C);
    d[0] = sp[0]; d[1] = sp[1]; d[2] = sp[2];
}

extern "C" void kernel_launch(void* const* d_in, const int* in_sizes, int n_in,
                              void* d_out, int out_size) {
    const float* pts = (const float*)d_in[0];
    float* out = (float*)d_out;
    fps_compact_kernel<<<B, NT>>>(pts);
    gather_kernel<<<(B * N) / 256, 256>>>(pts, out);
}

// round 2
// speedup vs baseline: 1.5921x; 1.5921x over previous
#include <cuda_runtime.h>
#include <cstdint>

#define B   64
#define N   65536
#define C   6
#define CPB 32                 // CTAs per batch for wide passes
#define TH  256
#define CHUNK (N / CPB)        // 2048 points per CTA
#define PPT   (CHUNK / TH)     // 8 points per thread
#define WIDE_GRID (B * CPB)    // 2048

// ---- __device__ scratch (allocation-free rule) ----
__device__ float4 g_xyz[B * N];            // packed xyz (64 MB, L2-resident)
__device__ float  g_pv[WIDE_GRID];         // partial argmax values
__device__ int    g_pi[WIDE_GRID];         // partial argmax indices (global)
__device__ float4 g_cent[B * 4];           // centers
__device__ unsigned g_maskbits[B * N / 32];// keep bitmask (512 KB)
__device__ int    g_idx[B * N];            // compacted kept indices
__device__ int    g_nv[B];                 // num_valid per batch

// warp argmax: value desc, index asc on ties
__device__ __forceinline__ void warp_argmax(float& best, int& bi) {
    #pragma unroll
    for (int o = 16; o; o >>= 1) {
        const float v = __shfl_down_sync(0xffffffffu, best, o);
        const int   j = __shfl_down_sync(0xffffffffu, bi,   o);
        if (v > best || (v == best && j < bi)) { best = v; bi = j; }
    }
}

__device__ __forceinline__ void block_partial_out(float best, int bi, int part_slot) {
    __shared__ float sv[8];
    __shared__ int   si[8];
    const int lane = threadIdx.x & 31, w = threadIdx.x >> 5;
    warp_argmax(best, bi);
    if (lane == 0) { sv[w] = best; si[w] = bi; }
    __syncthreads();
    if (threadIdx.x < 8) {
        best = sv[threadIdx.x]; bi = si[threadIdx.x];
        #pragma unroll
        for (int o = 4; o; o >>= 1) {
            const float v = __shfl_down_sync(0xffu, best, o);
            const int   j = __shfl_down_sync(0xffu, bi,   o);
            if (v > best || (v == best && j < bi)) { best = v; bi = j; }
        }
        if (threadIdx.x == 0) { g_pv[part_slot] = best; g_pi[part_slot] = bi; }
    }
}

// Pass 1: pack xyz -> float4, dist^2 to center 0, partial argmax.
__global__ __launch_bounds__(TH) void pack_kernel(const float* __restrict__ pts) {
    const int b   = blockIdx.x / CPB;
    const int cta = blockIdx.x % CPB;
    const float* P = pts + (size_t)b * N * C;
    const float c0x = P[0], c0y = P[1], c0z = P[2];

    float best = -1.0f; int bi = 0;
    #pragma unroll
    for (int k = 0; k < PPT; k++) {
        const int il = cta * CHUNK + threadIdx.x + k * TH;   // batch-local
        const int gi = b * N + il;                            // global point id
        const float* p = P + (size_t)il * C;
        const float2 xy = *(const float2*)p;
        const float  z  = p[2];
        g_xyz[gi] = make_float4(xy.x, xy.y, z, 0.0f);
        const float dx = xy.x - c0x, dy = xy.y - c0y, dz = z - c0z;
        const float md = dx * dx + dy * dy + dz * dz;
        if (md > best) { best = md; bi = gi; }
    }
    block_partial_out(best, bi, blockIdx.x);
}

// FPS step: min-dist over nc known centers (recomputed), partial argmax.
__global__ __launch_bounds__(TH) void step_kernel(int nc) {
    const int b   = blockIdx.x / CPB;
    const int cta = blockIdx.x % CPB;
    __shared__ float4 sc[4];
    if (threadIdx.x < nc) sc[threadIdx.x] = g_cent[b * 4 + threadIdx.x];
    __syncthreads();

    float best = -1.0f; int bi = 0;
    #pragma unroll
    for (int k = 0; k < PPT; k++) {
        const int gi = b * N + cta * CHUNK + threadIdx.x + k * TH;
        const float4 p = g_xyz[gi];
        float md = 1e10f;
        for (int cc = 0; cc < nc; cc++) {
            const float dx = p.x - sc[cc].x;
            const float dy = p.y - sc[cc].y;
            const float dz = p.z - sc[cc].z;
            md = fminf(md, dx * dx + dy * dy + dz * dz);
        }
        if (md > best) { best = md; bi = gi; }
    }
    block_partial_out(best, bi, blockIdx.x);
}

// Reduce partials -> center s+1 (and center 0 on s==0).
__global__ __launch_bounds__(32) void reduce_kernel(int s) {
    const int b = blockIdx.x;
    float best = g_pv[b * CPB + threadIdx.x];
    int   bi   = g_pi[b * CPB + threadIdx.x];
    warp_argmax(best, bi);
    if (threadIdx.x == 0) {
        if (s == 0) g_cent[b * 4 + 0] = g_xyz[b * N];
        g_cent[b * 4 + s + 1] = g_xyz[bi];
    }
}

// Keep bitmask: bit set iff sqrt(min dist^2 to 4 centers) >= 0.2.
__global__ __launch_bounds__(TH) void mask_kernel() {
    const int gi = blockIdx.x * TH + threadIdx.x;   // one thread per point
    const int b  = gi >> 16;
    const float4 p = g_xyz[gi];
    float md = 1e10f;
    #pragma unroll
    for (int cc = 0; cc < 4; cc++) {
        const float4 c = g_cent[b * 4 + cc];
        const float dx = p.x - c.x, dy = p.y - c.y, dz = p.z - c.z;
        md = fminf(md, dx * dx + dy * dy + dz * dz);
    }
    const bool keep = (__fsqrt_rn(md) >= 0.2f);
    const unsigned w = __ballot_sync(0xffffffffu, keep);
    if ((threadIdx.x & 31) == 0) g_maskbits[gi >> 5] = w;
}

// Stable compaction: one block per batch over the bitmask.
__global__ __launch_bounds__(1024) void compact_kernel() {
    const int b = blockIdx.x;
    const int t = threadIdx.x;
    const unsigned* mb = g_maskbits + b * (N / 32);
    const unsigned w0 = mb[t * 2], w1 = mb[t * 2 + 1];
    int cnt = __popc(w0) + __popc(w1);

    __shared__ int swarp[32];
    const int lane = t & 31, w = t >> 5;
    int inc = cnt;
    #pragma unroll
    for (int o = 1; o < 32; o <<= 1) {
        const int u = __shfl_up_sync(0xffffffffu, inc, o);
        if (lane >= o) inc += u;
    }
    if (lane == 31) swarp[w] = inc;
    __syncthreads();
    if (t < 32) {
        int v2 = swarp[t];
        #pragma unroll
        for (int o = 1; o < 32; o <<= 1) {
            const int u = __shfl_up_sync(0xffffffffu, v2, o);
            if (t >= o) v2 += u;
        }
        swarp[t] = v2;
    }
    __syncthreads();

    int off = inc - cnt + (w ? swarp[w - 1] : 0);
    int* ob = g_idx + b * N;
    const int base = t * 64;
    unsigned m = w0;
    while (m) { const int l = __ffs(m) - 1; m &= m - 1; ob[off++] = base + l; }
    m = w1;
    while (m) { const int l = __ffs(m) - 1; m &= m - 1; ob[off++] = base + 32 + l; }
    if (t == 0) g_nv[b] = swarp[31];
}

// out[b, j, :] = points[b, kept[j % nv], :]  (zeros if nv == 0)
__global__ __launch_bounds__(TH) void gather_kernel(const float* __restrict__ pts,
                                                    float* __restrict__ out) {
    const int tid = blockIdx.x * TH + threadIdx.x;
    const int b = tid >> 16;
    const int j = tid & (N - 1);
    const int nv = g_nv[b];
    float2* d = (float2*)(out + (size_t)tid * C);
    if (nv == 0) {
        const float2 z = make_float2(0.f, 0.f);
        d[0] = z; d[1] = z; d[2] = z;
        return;
    }
    const int k   = j % nv;
    const int src = g_idx[(b << 16) + k];
    const float2* sp = (const float2*)(pts + ((size_t)(b << 16) + src) * C);
    d[0] = sp[0]; d[1] = sp[1]; d[2] = sp[2];
}

extern "C" void kernel_launch(void* const* d_in, const int* in_sizes, int n_in,
                              void* d_out, int out_size) {
    const float* pts = (const float*)d_in[0];
    float* out = (float*)d_out;

    pack_kernel<<<WIDE_GRID, TH>>>(pts);
    reduce_kernel<<<B, 32>>>(0);
    step_kernel<<<WIDE_GRID, TH>>>(2);
    reduce_kernel<<<B, 32>>>(1);
    step_kernel<<<WIDE_GRID, TH>>>(3);
    reduce_kernel<<<B, 32>>>(2);
    mask_kernel<<<B * N / TH, TH>>>();
    compact_kernel<<<B, 1024>>>();
    gather_kernel<<<B * N / TH, TH>>>(pts, out);
}